// round 4
// baseline (speedup 1.0000x reference)
#include <cuda_runtime.h>
#include <cstdint>
#include <cstddef>

// ---------------- problem constants ----------------
#define Hd   1024
#define Bsz  32
#define Tlen 512
#define GH   (4*Hd)
#define NBLK 128      // recurrence blocks (one per SM, single wave)
#define HPB  8        // h columns per block
#define LDP  36       // Gpart padded stride (conflict-free for our patterns)

// ---------------- device scratch (no cudaMalloc allowed) ----------------
__device__ float g_xg[(size_t)Tlen * Bsz * GH];   // 256 MB: xg for current layer
__device__ float g_a4[(size_t)Tlen * Bsz * Hd];   // 64 MB: tf32-rounded GEMM A
__device__ float g_w4[2 * (size_t)GH * Hd];       // 32 MB: tf32-rounded W0|W1
__device__ float g_h[Bsz * Hd];                   // current hidden state (tf32-rounded)
__device__ unsigned g_barcnt;
__device__ volatile unsigned g_bargen;

// ---------------- small helpers ----------------
__device__ __forceinline__ uint32_t f2tf(float x) {
    uint32_t r;
    asm("cvt.rna.tf32.f32 %0, %1;" : "=r"(r) : "f"(x));
    return r;
}
__device__ __forceinline__ float sigmoidf_(float x) {
    return 1.0f / (1.0f + __expf(-x));
}
__device__ __forceinline__ void cpasync16(float* s, const float* g) {
    uint32_t sa = (uint32_t)__cvta_generic_to_shared(s);
    asm volatile("cp.async.cg.shared.global [%0], [%1], 16;" :: "r"(sa), "l"(g));
}
__device__ __forceinline__ void cp_commit()  { asm volatile("cp.async.commit_group;"); }
__device__ __forceinline__ void cp_wait_1()  { asm volatile("cp.async.wait_group 1;"); }
__device__ __forceinline__ void cp_wait_0()  { asm volatile("cp.async.wait_group 0;"); }

__device__ __forceinline__ void mma_tf32(float* c, uint32_t a0, uint32_t a1,
                                         uint32_t a2, uint32_t a3,
                                         uint32_t b0, uint32_t b1) {
    asm volatile(
        "mma.sync.aligned.m16n8k8.row.col.f32.tf32.tf32.f32 "
        "{%0,%1,%2,%3},{%4,%5,%6,%7},{%8,%9},{%0,%1,%2,%3};"
        : "+f"(c[0]), "+f"(c[1]), "+f"(c[2]), "+f"(c[3])
        : "r"(a0), "r"(a1), "r"(a2), "r"(a3), "r"(b0), "r"(b1));
}

// grid-wide sense-reversing barrier (all NBLK blocks co-resident).
__device__ __forceinline__ void grid_barrier() {
    __syncthreads();
    if (threadIdx.x == 0) {
        unsigned gen = g_bargen;
        __threadfence();
        if (atomicAdd(&g_barcnt, 1u) == NBLK - 1) {
            g_barcnt = 0;
            __threadfence();
            g_bargen = gen + 1;
        } else {
            while (g_bargen == gen) { __nanosleep(64); }
            __threadfence();
        }
    }
    __syncthreads();
}

// tiny kernel: resets barrier state; also shifts the ncu -s 5 capture window
// so the 6th launch is sublstm_rec (we want its profile).
__global__ void bar_reset_kernel() {
    if (threadIdx.x == 0) { g_barcnt = 0; g_bargen = 0; }
}

// =====================================================================
// round-to-tf32 copy (pre-pass so GEMM needs no cvt in its hot loop)
// =====================================================================
__global__ void __launch_bounds__(256) round_tf32_kernel(
    const float* __restrict__ src, float* __restrict__ dst, int n4)
{
    int i = blockIdx.x * blockDim.x + threadIdx.x;
    int stride = gridDim.x * blockDim.x;
    for (; i < n4; i += stride) {
        float4 v = ((const float4*)src)[i];
        v.x = __uint_as_float(f2tf(v.x));
        v.y = __uint_as_float(f2tf(v.y));
        v.z = __uint_as_float(f2tf(v.z));
        v.w = __uint_as_float(f2tf(v.w));
        ((float4*)dst)[i] = v;
    }
}

// =====================================================================
// GEMM: C[M,N] = A[M,1024] @ B[N,1024]^T + bias1[N] + bias2[N]
// A, B pre-rounded to tf32. Fragment loads use lds.128 with the K
// permutation (position lc -> col 4lc+2p, lc+4 -> 4lc+2p+1) applied to
// BOTH operands, so dot products are unchanged and the C layout is the
// standard one. 16 lds.128 + 32 mma per BK=32 iteration.
// =====================================================================
#define BM 128
#define BN 64
#define BK 32
#define LDT (BK + 4)

__global__ void __launch_bounds__(256) gemm_bias_tf32(
    const float* __restrict__ A, const float* __restrict__ Bw,
    const float* __restrict__ bias1, const float* __restrict__ bias2,
    float* __restrict__ C, int M, int N)
{
    extern __shared__ float sm[];
    const int K = 1024;
    float* As = sm;                 // [2][BM][LDT]
    float* Bs = sm + 2 * BM * LDT;  // [2][BN][LDT]

    const int tid  = threadIdx.x;
    const int lane = tid & 31, wid = tid >> 5;
    const int wm = wid & 3, wn = wid >> 2;       // 4 x 2 warp grid, warp tile 32x32
    const int lr = lane >> 2, lc = lane & 3;
    const int bn = blockIdx.x, bm = blockIdx.y;

    const float* Ab = A  + (size_t)bm * BM * K;
    const float* Bb = Bw + (size_t)bn * BN * K;

    float acc[2][4][4];
    #pragma unroll
    for (int i = 0; i < 2; i++)
        #pragma unroll
        for (int j = 0; j < 4; j++)
            #pragma unroll
            for (int k = 0; k < 4; k++) acc[i][j][k] = 0.f;

    auto load_tiles = [&](int st, int kb) {
        float* ad = As + st * BM * LDT;
        #pragma unroll
        for (int i = 0; i < 4; i++) {
            int s = tid + i * 256;
            int row = s >> 3, sc = s & 7;
            cpasync16(ad + row * LDT + sc * 4, Ab + (size_t)row * K + kb * BK + sc * 4);
        }
        float* bd = Bs + st * BN * LDT;
        #pragma unroll
        for (int i = 0; i < 2; i++) {
            int s = tid + i * 256;
            int row = s >> 3, sc = s & 7;
            cpasync16(bd + row * LDT + sc * 4, Bb + (size_t)row * K + kb * BK + sc * 4);
        }
    };

    load_tiles(0, 0);
    cp_commit();

    const int NKB = K / BK; // 32
    for (int kb = 0; kb < NKB; kb++) {
        if (kb + 1 < NKB) { load_tiles((kb + 1) & 1, kb + 1); cp_commit(); cp_wait_1(); }
        else              { cp_wait_0(); }
        __syncthreads();

        const float* as = As + (kb & 1) * BM * LDT + (wm * 32 + lr) * LDT + 4 * lc;
        const float* bs = Bs + (kb & 1) * BN * LDT + (wn * 32 + lr) * LDT + 4 * lc;

        #pragma unroll
        for (int grp = 0; grp < 2; grp++) {
            float4 va[4], vb[4];
            #pragma unroll
            for (int mr = 0; mr < 4; mr++)
                va[mr] = *(const float4*)(as + mr * 8 * LDT + grp * 16);
            #pragma unroll
            for (int nt = 0; nt < 4; nt++)
                vb[nt] = *(const float4*)(bs + nt * 8 * LDT + grp * 16);

            #pragma unroll
            for (int p = 0; p < 2; p++) {
                #pragma unroll
                for (int nt = 0; nt < 4; nt++) {
                    const float* b = (const float*)&vb[nt];
                    const uint32_t b0 = __float_as_uint(b[2 * p]);
                    const uint32_t b1 = __float_as_uint(b[2 * p + 1]);
                    #pragma unroll
                    for (int mt = 0; mt < 2; mt++) {
                        const float* a0 = (const float*)&va[2 * mt];
                        const float* a1 = (const float*)&va[2 * mt + 1];
                        mma_tf32(acc[mt][nt],
                                 __float_as_uint(a0[2 * p]),
                                 __float_as_uint(a1[2 * p]),
                                 __float_as_uint(a0[2 * p + 1]),
                                 __float_as_uint(a1[2 * p + 1]),
                                 b0, b1);
                    }
                }
            }
        }
        __syncthreads();
    }

    #pragma unroll
    for (int mt = 0; mt < 2; mt++) {
        int m0 = bm * BM + wm * 32 + mt * 16 + lr;
        #pragma unroll
        for (int nt = 0; nt < 4; nt++) {
            int n0 = bn * BN + wn * 32 + nt * 8 + 2 * lc;
            float bv0 = bias1[n0] + bias2[n0];
            float bv1 = bias1[n0 + 1] + bias2[n0 + 1];
            float2 v0 = make_float2(acc[mt][nt][0] + bv0, acc[mt][nt][1] + bv1);
            float2 v1 = make_float2(acc[mt][nt][2] + bv0, acc[mt][nt][3] + bv1);
            *(float2*)(C + (size_t)m0 * N + n0)       = v0;
            *(float2*)(C + (size_t)(m0 + 8) * N + n0) = v1;
        }
    }
}

// =====================================================================
// Persistent subLSTM recurrence (register-resident R). Unchanged from
// the passing Round-3 kernel except cosmetics.
// =====================================================================
__global__ void __launch_bounds__(256, 1) sublstm_rec(
    const float* __restrict__ xg, const float* __restrict__ R,
    const float* __restrict__ h0, const float* __restrict__ c0,
    float* __restrict__ out, float* __restrict__ hT, float* __restrict__ cT,
    int round_output)
{
    __shared__ float Gpart[8 * 32 * LDP];   // 36,864 B

    const int tid  = threadIdx.x;
    const int lane = tid & 31;
    const int kw   = tid >> 5;              // K-split index 0..7
    const int lr   = lane >> 2, lc = lane & 3;
    const int bid  = blockIdx.x;

    // ---- load R slice into registers (once), tf32 + K-permutation ----
    uint32_t b[16][4][2];
    #pragma unroll
    for (int f = 0; f < 16; f++) {
        const int kb = kw * 128 + (f >> 1) * 16;
        const int p  = f & 1;
        #pragma unroll
        for (int nt = 0; nt < 4; nt++) {
            const int gr = nt * Hd + bid * HPB + lr;   // global gate row
            const float2 rv = *(const float2*)(R + (size_t)gr * Hd + kb + 4 * lc + 2 * p);
            b[f][nt][0] = f2tf(rv.x);
            b[f][nt][1] = f2tf(rv.y);
        }
    }

    // ---- per-thread cell state: thread -> (batch m, local col jl) ----
    const int m  = tid >> 3;
    const int jl = tid & 7;
    const int jg = bid * HPB + jl;
    float c = c0[m * Hd + jg];
    __stcg(&g_h[m * Hd + jg], __uint_as_float(f2tf(h0[m * Hd + jg])));

    // xg prefetch for step 0 (bh already folded into xg by the GEMM bias)
    float xv0 = __ldg(&xg[(size_t)m * GH + 0 * Hd + jg]);
    float xv1 = __ldg(&xg[(size_t)m * GH + 1 * Hd + jg]);
    float xv2 = __ldg(&xg[(size_t)m * GH + 2 * Hd + jg]);
    float xv3 = __ldg(&xg[(size_t)m * GH + 3 * Hd + jg]);

    grid_barrier();   // g_h init visible everywhere

    const float* gh0 = g_h + (size_t)lr * Hd + kw * 128 + 4 * lc;

    for (int t = 0; t < Tlen; t++) {
        float acc[2][4][4];
        #pragma unroll
        for (int i = 0; i < 2; i++)
            #pragma unroll
            for (int j = 0; j < 4; j++)
                #pragma unroll
                for (int k = 0; k < 4; k++) acc[i][j][k] = 0.f;

        #pragma unroll
        for (int grp = 0; grp < 8; grp++) {
            const float* hp = gh0 + grp * 16;
            float4 v[2][2];                       // [mf][half]: rows mf*16+lr, +8
            v[0][0] = __ldcg((const float4*)(hp));
            v[0][1] = __ldcg((const float4*)(hp +  8 * Hd));
            v[1][0] = __ldcg((const float4*)(hp + 16 * Hd));
            v[1][1] = __ldcg((const float4*)(hp + 24 * Hd));
            #pragma unroll
            for (int p = 0; p < 2; p++) {
                const int f = grp * 2 + p;
                uint32_t a[2][4];
                #pragma unroll
                for (int mf = 0; mf < 2; mf++) {
                    const float* lo = (const float*)&v[mf][0];
                    const float* hi = (const float*)&v[mf][1];
                    a[mf][0] = __float_as_uint(lo[2 * p]);
                    a[mf][1] = __float_as_uint(hi[2 * p]);
                    a[mf][2] = __float_as_uint(lo[2 * p + 1]);
                    a[mf][3] = __float_as_uint(hi[2 * p + 1]);
                }
                #pragma unroll
                for (int nt = 0; nt < 4; nt++)
                    #pragma unroll
                    for (int mf = 0; mf < 2; mf++)
                        mma_tf32(acc[mf][nt], a[mf][0], a[mf][1], a[mf][2], a[mf][3],
                                 b[f][nt][0], b[f][nt][1]);
            }
        }

        // ---- cross-warp K reduction via smem ----
        #pragma unroll
        for (int mf = 0; mf < 2; mf++)
            #pragma unroll
            for (int nt = 0; nt < 4; nt++)
                #pragma unroll
                for (int cc = 0; cc < 4; cc++) {
                    const int r = mf * 16 + lr + ((cc >> 1) << 3);
                    const int n = nt * 8 + 2 * lc + (cc & 1);
                    Gpart[(kw * 32 + n) * LDP + r] = acc[mf][nt][cc];
                }
        __syncthreads();

        // ---- epilogue: thread (m, jl) computes its cell ----
        float pre[4];
        #pragma unroll
        for (int g = 0; g < 4; g++) {
            const int n = g * 8 + jl;
            float s = Gpart[(0 * 32 + n) * LDP + m];
            #pragma unroll
            for (int k = 1; k < 8; k++) s += Gpart[(k * 32 + n) * LDP + m];
            pre[g] = s;
        }
        const float ig = sigmoidf_(pre[0] + xv0);
        const float og = sigmoidf_(pre[1] + xv1);
        const float zg = sigmoidf_(pre[2] + xv2);
        const float fg = sigmoidf_(pre[3] + xv3);
        c = c * fg + zg - ig;                 // subtractive cell update
        const float h = sigmoidf_(c) - og;    // subtractive output
        const float hr = __uint_as_float(f2tf(h));

        out[(size_t)t * Bsz * Hd + m * Hd + jg] = round_output ? hr : h;
        __stcg(&g_h[m * Hd + jg], hr);
        if (t == Tlen - 1) {
            hT[m * Hd + jg] = h;
            cT[m * Hd + jg] = c;
        }

        // prefetch next step's xg while the barrier drains
        const int tn = (t + 1 < Tlen) ? t + 1 : t;
        const size_t xb = (size_t)tn * Bsz * GH + (size_t)m * GH + jg;
        xv0 = __ldg(&xg[xb + 0 * Hd]);
        xv1 = __ldg(&xg[xb + 1 * Hd]);
        xv2 = __ldg(&xg[xb + 2 * Hd]);
        xv3 = __ldg(&xg[xb + 3 * Hd]);

        grid_barrier();
    }
}

// =====================================================================
// launch
// =====================================================================
extern "C" void kernel_launch(void* const* d_in, const int* in_sizes, int n_in,
                              void* d_out, int out_size)
{
    const float* x   = (const float*)d_in[0];
    const float* h0  = (const float*)d_in[1];
    const float* c0  = (const float*)d_in[2];
    const float* W0  = (const float*)d_in[3];
    const float* R0  = (const float*)d_in[4];
    const float* bi0 = (const float*)d_in[5];
    const float* bh0 = (const float*)d_in[6];
    const float* W1  = (const float*)d_in[7];
    const float* R1  = (const float*)d_in[8];
    const float* bi1 = (const float*)d_in[9];
    const float* bh1 = (const float*)d_in[10];

    float* out = (float*)d_out;                       // [T,B,H]
    float* hTs = out + (size_t)Tlen * Bsz * Hd;       // [2,B,H]
    float* cTs = hTs + 2 * (size_t)Bsz * Hd;          // [2,B,H]

    float *xg_p, *a4_p, *w4_p;
    cudaGetSymbolAddress((void**)&xg_p, g_xg);
    cudaGetSymbolAddress((void**)&a4_p, g_a4);
    cudaGetSymbolAddress((void**)&w4_p, g_w4);

    const int SMEM_G = 2 * (BM + BN) * LDT * (int)sizeof(float);
    cudaFuncSetAttribute(gemm_bias_tf32, cudaFuncAttributeMaxDynamicSharedMemorySize, SMEM_G);

    dim3 gg(GH / BN, (Tlen * Bsz) / BM);  // (64, 128)
    const int MR = Tlen * Bsz * Hd / 4;   // float4 count for A-size arrays
    const int WR = GH * Hd / 4;           // float4 count for one W

    // pre-round weights (both layers) and layer-0 A          (launches 1-3)
    round_tf32_kernel<<<512, 256>>>(W0, w4_p, WR);
    round_tf32_kernel<<<512, 256>>>(W1, w4_p + (size_t)GH * Hd, WR);
    round_tf32_kernel<<<1024, 256>>>(x, a4_p, MR);

    // layer 0                                                 (launches 4-6)
    gemm_bias_tf32<<<gg, 256, SMEM_G>>>(a4_p, w4_p, bi0, bh0, xg_p, Tlen * Bsz, GH);
    bar_reset_kernel<<<1, 32>>>();   // shifts ncu -s 5 window onto sublstm_rec
    sublstm_rec<<<NBLK, 256>>>(xg_p, R0, h0, c0, a4_p, hTs, cTs, 1);

    // layer 1                                                 (launches 7-8)
    gemm_bias_tf32<<<gg, 256, SMEM_G>>>(a4_p, w4_p + (size_t)GH * Hd, bi1, bh1,
                                        xg_p, Tlen * Bsz, GH);
    sublstm_rec<<<NBLK, 256>>>(xg_p, R1, h0 + Bsz * Hd, c0 + Bsz * Hd,
                               out, hTs + Bsz * Hd, cTs + Bsz * Hd, 0);
}

// round 6
// speedup vs baseline: 1.0531x; 1.0531x over previous
#include <cuda_runtime.h>
#include <cstdint>
#include <cstddef>

// ---------------- problem constants ----------------
#define Hd   1024
#define Bsz  32
#define Tlen 512
#define GH   (4*Hd)
#define NBLK 128      // recurrence blocks (one per SM, single wave)
#define HPB  8        // h columns per block
#define LDP  36       // Gpart padded stride (conflict-free for our patterns)
#define NLEAF 8       // barrier tree fan-in (128 = 8 leaves x 16)

// ---------------- device scratch (no cudaMalloc allowed) ----------------
__device__ float g_xg[(size_t)Tlen * Bsz * GH];   // 256 MB: xg for current layer
__device__ float g_a4[(size_t)Tlen * Bsz * Hd];   // 64 MB: tf32-rounded GEMM A
__device__ float g_w4[2 * (size_t)GH * Hd];       // 32 MB: tf32-rounded W0|W1
__device__ float g_hbuf[2][Bsz * Hd];             // double-buffered hidden state
__device__ unsigned g_leaf[NLEAF * 64];           // leaf counters, 256B stride
__device__ unsigned g_root;                       // root counter
__device__ volatile unsigned g_bargen;            // published generation

// ---------------- small helpers ----------------
__device__ __forceinline__ uint32_t f2tf(float x) {
    uint32_t r;
    asm("cvt.rna.tf32.f32 %0, %1;" : "=r"(r) : "f"(x));
    return r;
}
__device__ __forceinline__ float sigmoidf_(float x) {
    return 1.0f / (1.0f + __expf(-x));
}
__device__ __forceinline__ void cpasync16(float* s, const float* g) {
    uint32_t sa = (uint32_t)__cvta_generic_to_shared(s);
    asm volatile("cp.async.cg.shared.global [%0], [%1], 16;" :: "r"(sa), "l"(g));
}
__device__ __forceinline__ void cp_commit()  { asm volatile("cp.async.commit_group;"); }
__device__ __forceinline__ void cp_wait_1()  { asm volatile("cp.async.wait_group 1;"); }
__device__ __forceinline__ void cp_wait_0()  { asm volatile("cp.async.wait_group 0;"); }

__device__ __forceinline__ void mma_tf32(float* c, uint32_t a0, uint32_t a1,
                                         uint32_t a2, uint32_t a3,
                                         uint32_t b0, uint32_t b1) {
    asm volatile(
        "mma.sync.aligned.m16n8k8.row.col.f32.tf32.tf32.f32 "
        "{%0,%1,%2,%3},{%4,%5,%6,%7},{%8,%9},{%0,%1,%2,%3};"
        : "+f"(c[0]), "+f"(c[1]), "+f"(c[2]), "+f"(c[3])
        : "r"(a0), "r"(a1), "r"(a2), "r"(a3), "r"(b0), "r"(b1));
}

// ---------------------------------------------------------------------
// Grid barrier: 2-level atomic tree (same primitive as the barrier that
// passed in rounds 1/3, but arrival is 8-way parallel instead of one
// serialized 128-deep atomic chain). Publisher resets counters BEFORE
// bumping g_bargen; arrivals for the next phase can only start after
// spinners observe the bump, so no reset race.
// ---------------------------------------------------------------------
__device__ __forceinline__ void grid_barrier() {
    __syncthreads();
    if (threadIdx.x == 0) {
        const unsigned gen = g_bargen;
        __threadfence();   // release this block's h writes
        const unsigned leaf = blockIdx.x & (NLEAF - 1);
        if (atomicAdd(&g_leaf[leaf * 64], 1u) == (NBLK / NLEAF) - 1) {
            if (atomicAdd(&g_root, 1u) == NLEAF - 1) {
                g_root = 0;
                #pragma unroll
                for (int i = 0; i < NLEAF; i++) g_leaf[i * 64] = 0;
                __threadfence();
                g_bargen = gen + 1;
            } else {
                while (g_bargen == gen) { __nanosleep(32); }
            }
        } else {
            while (g_bargen == gen) { __nanosleep(32); }
        }
        __threadfence();   // acquire everyone's h writes
    }
    __syncthreads();
}

// reset barrier state before each persistent-kernel launch (graph-safe)
__global__ void bar_reset_kernel() {
    if (threadIdx.x < NLEAF) g_leaf[threadIdx.x * 64] = 0;
    if (threadIdx.x == 0) { g_root = 0; g_bargen = 0; }
}

// =====================================================================
// round-to-tf32 copy (pre-pass so GEMM needs no cvt in its hot loop)
// =====================================================================
__global__ void __launch_bounds__(256) round_tf32_kernel(
    const float* __restrict__ src, float* __restrict__ dst, int n4)
{
    int i = blockIdx.x * blockDim.x + threadIdx.x;
    int stride = gridDim.x * blockDim.x;
    for (; i < n4; i += stride) {
        float4 v = ((const float4*)src)[i];
        v.x = __uint_as_float(f2tf(v.x));
        v.y = __uint_as_float(f2tf(v.y));
        v.z = __uint_as_float(f2tf(v.z));
        v.w = __uint_as_float(f2tf(v.w));
        ((float4*)dst)[i] = v;
    }
}

// =====================================================================
// GEMM: C[M,N] = A[M,1024] @ B[N,1024]^T + bias1[N] + bias2[N]
// (Round-3 body verbatim: LDS.32 fragment loads, 64 regs, tensor ~50%.)
// =====================================================================
#define BM 128
#define BN 64
#define BK 32
#define LDT (BK + 4)

__global__ void __launch_bounds__(256) gemm_bias_tf32(
    const float* __restrict__ A, const float* __restrict__ Bw,
    const float* __restrict__ bias1, const float* __restrict__ bias2,
    float* __restrict__ C, int M, int N)
{
    extern __shared__ float sm[];
    const int K = 1024;
    float* As = sm;                 // [2][BM][LDT]
    float* Bs = sm + 2 * BM * LDT;  // [2][BN][LDT]

    const int tid  = threadIdx.x;
    const int lane = tid & 31, wid = tid >> 5;
    const int wm = wid & 3, wn = wid >> 2;       // 4 x 2 warp grid, warp tile 32x32
    const int lr = lane >> 2, lc = lane & 3;
    const int bn = blockIdx.x, bm = blockIdx.y;

    const float* Ab = A  + (size_t)bm * BM * K;
    const float* Bb = Bw + (size_t)bn * BN * K;

    float acc[2][4][4];
    #pragma unroll
    for (int i = 0; i < 2; i++)
        #pragma unroll
        for (int j = 0; j < 4; j++)
            #pragma unroll
            for (int k = 0; k < 4; k++) acc[i][j][k] = 0.f;

    auto load_tiles = [&](int st, int kb) {
        float* ad = As + st * BM * LDT;
        #pragma unroll
        for (int i = 0; i < 4; i++) {
            int s = tid + i * 256;
            int row = s >> 3, sc = s & 7;
            cpasync16(ad + row * LDT + sc * 4, Ab + (size_t)row * K + kb * BK + sc * 4);
        }
        float* bd = Bs + st * BN * LDT;
        #pragma unroll
        for (int i = 0; i < 2; i++) {
            int s = tid + i * 256;
            int row = s >> 3, sc = s & 7;
            cpasync16(bd + row * LDT + sc * 4, Bb + (size_t)row * K + kb * BK + sc * 4);
        }
    };

    load_tiles(0, 0);
    cp_commit();

    const int NKB = K / BK; // 32
    for (int kb = 0; kb < NKB; kb++) {
        if (kb + 1 < NKB) { load_tiles((kb + 1) & 1, kb + 1); cp_commit(); cp_wait_1(); }
        else              { cp_wait_0(); }
        __syncthreads();

        const float* as = As + (kb & 1) * BM * LDT + (wm * 32 + lr) * LDT + lc;
        const float* bs = Bs + (kb & 1) * BN * LDT + (wn * 32 + lr) * LDT + lc;

        #pragma unroll
        for (int kk = 0; kk < 4; kk++) {
            uint32_t a[2][4];
            #pragma unroll
            for (int mt = 0; mt < 2; mt++) {
                const float* ap = as + mt * 16 * LDT + kk * 8;
                a[mt][0] = __float_as_uint(ap[0]);
                a[mt][1] = __float_as_uint(ap[8 * LDT]);
                a[mt][2] = __float_as_uint(ap[4]);
                a[mt][3] = __float_as_uint(ap[8 * LDT + 4]);
            }
            #pragma unroll
            for (int nt = 0; nt < 4; nt++) {
                const float* bp = bs + nt * 8 * LDT + kk * 8;
                uint32_t b0 = __float_as_uint(bp[0]);
                uint32_t b1 = __float_as_uint(bp[4]);
                #pragma unroll
                for (int mt = 0; mt < 2; mt++)
                    mma_tf32(acc[mt][nt], a[mt][0], a[mt][1], a[mt][2], a[mt][3], b0, b1);
            }
        }
        __syncthreads();
    }

    #pragma unroll
    for (int mt = 0; mt < 2; mt++) {
        int m0 = bm * BM + wm * 32 + mt * 16 + lr;
        #pragma unroll
        for (int nt = 0; nt < 4; nt++) {
            int n0 = bn * BN + wn * 32 + nt * 8 + 2 * lc;
            float bv0 = bias1[n0] + bias2[n0];
            float bv1 = bias1[n0 + 1] + bias2[n0 + 1];
            float2 v0 = make_float2(acc[mt][nt][0] + bv0, acc[mt][nt][1] + bv1);
            float2 v1 = make_float2(acc[mt][nt][2] + bv0, acc[mt][nt][3] + bv1);
            *(float2*)(C + (size_t)m0 * N + n0)       = v0;
            *(float2*)(C + (size_t)(m0 + 8) * N + n0) = v1;
        }
    }
}

// =====================================================================
// Persistent subLSTM recurrence (register-resident R, double-buffered h,
// tree atomic barrier). Compute core identical to the verified Round-3 body.
// =====================================================================
__global__ void __launch_bounds__(256, 1) sublstm_rec(
    const float* __restrict__ xg, const float* __restrict__ R,
    const float* __restrict__ h0, const float* __restrict__ c0,
    float* __restrict__ out, float* __restrict__ hT, float* __restrict__ cT,
    int round_output)
{
    __shared__ float Gpart[8 * 32 * LDP];   // 36,864 B

    const int tid  = threadIdx.x;
    const int lane = tid & 31;
    const int kw   = tid >> 5;              // K-split index 0..7
    const int lr   = lane >> 2, lc = lane & 3;
    const int bid  = blockIdx.x;

    // ---- load R slice into registers (once), tf32 + K-permutation ----
    uint32_t b[16][4][2];
    #pragma unroll
    for (int f = 0; f < 16; f++) {
        const int kb = kw * 128 + (f >> 1) * 16;
        const int p  = f & 1;
        #pragma unroll
        for (int nt = 0; nt < 4; nt++) {
            const int gr = nt * Hd + bid * HPB + lr;   // global gate row
            const float2 rv = *(const float2*)(R + (size_t)gr * Hd + kb + 4 * lc + 2 * p);
            b[f][nt][0] = f2tf(rv.x);
            b[f][nt][1] = f2tf(rv.y);
        }
    }

    // ---- per-thread cell state: thread -> (batch m, local col jl) ----
    const int m  = tid >> 3;
    const int jl = tid & 7;
    const int jg = bid * HPB + jl;
    float c = c0[m * Hd + jg];
    __stcg(&g_hbuf[0][m * Hd + jg], __uint_as_float(f2tf(h0[m * Hd + jg])));

    // xg prefetch for step 0 (bh already folded into xg by the GEMM bias)
    float xv0 = __ldg(&xg[(size_t)m * GH + 0 * Hd + jg]);
    float xv1 = __ldg(&xg[(size_t)m * GH + 1 * Hd + jg]);
    float xv2 = __ldg(&xg[(size_t)m * GH + 2 * Hd + jg]);
    float xv3 = __ldg(&xg[(size_t)m * GH + 3 * Hd + jg]);

    grid_barrier();   // g_hbuf[0] init visible everywhere

    const size_t hoff = (size_t)lr * Hd + kw * 128 + 4 * lc;

    for (int t = 0; t < Tlen; t++) {
        const float* gh0 = g_hbuf[t & 1] + hoff;      // read buffer
        float* const  wh = g_hbuf[(t + 1) & 1];       // write buffer

        float acc[2][4][4];
        #pragma unroll
        for (int i = 0; i < 2; i++)
            #pragma unroll
            for (int j = 0; j < 4; j++)
                #pragma unroll
                for (int k = 0; k < 4; k++) acc[i][j][k] = 0.f;

        #pragma unroll
        for (int grp = 0; grp < 8; grp++) {
            const float* hp = gh0 + grp * 16;
            float4 v[2][2];                       // [mf][half]: rows mf*16+lr, +8
            v[0][0] = __ldcg((const float4*)(hp));
            v[0][1] = __ldcg((const float4*)(hp +  8 * Hd));
            v[1][0] = __ldcg((const float4*)(hp + 16 * Hd));
            v[1][1] = __ldcg((const float4*)(hp + 24 * Hd));
            #pragma unroll
            for (int p = 0; p < 2; p++) {
                const int f = grp * 2 + p;
                uint32_t a[2][4];
                #pragma unroll
                for (int mf = 0; mf < 2; mf++) {
                    const float* lo = (const float*)&v[mf][0];
                    const float* hi = (const float*)&v[mf][1];
                    a[mf][0] = __float_as_uint(lo[2 * p]);
                    a[mf][1] = __float_as_uint(hi[2 * p]);
                    a[mf][2] = __float_as_uint(lo[2 * p + 1]);
                    a[mf][3] = __float_as_uint(hi[2 * p + 1]);
                }
                #pragma unroll
                for (int nt = 0; nt < 4; nt++)
                    #pragma unroll
                    for (int mf = 0; mf < 2; mf++)
                        mma_tf32(acc[mf][nt], a[mf][0], a[mf][1], a[mf][2], a[mf][3],
                                 b[f][nt][0], b[f][nt][1]);
            }
        }

        // ---- cross-warp K reduction via smem ----
        #pragma unroll
        for (int mf = 0; mf < 2; mf++)
            #pragma unroll
            for (int nt = 0; nt < 4; nt++)
                #pragma unroll
                for (int cc = 0; cc < 4; cc++) {
                    const int r = mf * 16 + lr + ((cc >> 1) << 3);
                    const int n = nt * 8 + 2 * lc + (cc & 1);
                    Gpart[(kw * 32 + n) * LDP + r] = acc[mf][nt][cc];
                }
        __syncthreads();

        // ---- epilogue: thread (m, jl) computes its cell ----
        float pre[4];
        #pragma unroll
        for (int g = 0; g < 4; g++) {
            const int n = g * 8 + jl;
            float s = Gpart[(0 * 32 + n) * LDP + m];
            #pragma unroll
            for (int k = 1; k < 8; k++) s += Gpart[(k * 32 + n) * LDP + m];
            pre[g] = s;
        }
        const float ig = sigmoidf_(pre[0] + xv0);
        const float og = sigmoidf_(pre[1] + xv1);
        const float zg = sigmoidf_(pre[2] + xv2);
        const float fg = sigmoidf_(pre[3] + xv3);
        c = c * fg + zg - ig;                 // subtractive cell update
        const float h = sigmoidf_(c) - og;    // subtractive output
        const float hr = __uint_as_float(f2tf(h));

        out[(size_t)t * Bsz * Hd + m * Hd + jg] = round_output ? hr : h;
        __stcg(&wh[m * Hd + jg], hr);
        if (t == Tlen - 1) {
            hT[m * Hd + jg] = h;
            cT[m * Hd + jg] = c;
        }

        // prefetch next step's xg while the barrier drains
        const int tn = (t + 1 < Tlen) ? t + 1 : t;
        const size_t xb = (size_t)tn * Bsz * GH + (size_t)m * GH + jg;
        xv0 = __ldg(&xg[xb + 0 * Hd]);
        xv1 = __ldg(&xg[xb + 1 * Hd]);
        xv2 = __ldg(&xg[xb + 2 * Hd]);
        xv3 = __ldg(&xg[xb + 3 * Hd]);

        grid_barrier();
    }
}

// =====================================================================
// launch
// =====================================================================
extern "C" void kernel_launch(void* const* d_in, const int* in_sizes, int n_in,
                              void* d_out, int out_size)
{
    const float* x   = (const float*)d_in[0];
    const float* h0  = (const float*)d_in[1];
    const float* c0  = (const float*)d_in[2];
    const float* W0  = (const float*)d_in[3];
    const float* R0  = (const float*)d_in[4];
    const float* bi0 = (const float*)d_in[5];
    const float* bh0 = (const float*)d_in[6];
    const float* W1  = (const float*)d_in[7];
    const float* R1  = (const float*)d_in[8];
    const float* bi1 = (const float*)d_in[9];
    const float* bh1 = (const float*)d_in[10];

    float* out = (float*)d_out;                       // [T,B,H]
    float* hTs = out + (size_t)Tlen * Bsz * Hd;       // [2,B,H]
    float* cTs = hTs + 2 * (size_t)Bsz * Hd;          // [2,B,H]

    float *xg_p, *a4_p, *w4_p;
    cudaGetSymbolAddress((void**)&xg_p, g_xg);
    cudaGetSymbolAddress((void**)&a4_p, g_a4);
    cudaGetSymbolAddress((void**)&w4_p, g_w4);

    const int SMEM_G = 2 * (BM + BN) * LDT * (int)sizeof(float);
    cudaFuncSetAttribute(gemm_bias_tf32, cudaFuncAttributeMaxDynamicSharedMemorySize, SMEM_G);

    dim3 gg(GH / BN, (Tlen * Bsz) / BM);  // (64, 128)
    const int MR = Tlen * Bsz * Hd / 4;   // float4 count for A-size arrays
    const int WR = GH * Hd / 4;           // float4 count for one W

    // pre-round weights (both layers) and layer-0 A
    round_tf32_kernel<<<512, 256>>>(W0, w4_p, WR);
    round_tf32_kernel<<<512, 256>>>(W1, w4_p + (size_t)GH * Hd, WR);
    round_tf32_kernel<<<1024, 256>>>(x, a4_p, MR);

    // layer 0: GEMM -> recurrence (hidden stream, tf32-rounded, lands in g_a4
    // which is exactly the layer-1 GEMM's A operand)
    gemm_bias_tf32<<<gg, 256, SMEM_G>>>(a4_p, w4_p, bi0, bh0, xg_p, Tlen * Bsz, GH);
    bar_reset_kernel<<<1, 128>>>();
    sublstm_rec<<<NBLK, 256>>>(xg_p, R0, h0, c0, a4_p, hTs, cTs, 1);

    // layer 1
    gemm_bias_tf32<<<gg, 256, SMEM_G>>>(a4_p, w4_p + (size_t)GH * Hd, bi1, bh1,
                                        xg_p, Tlen * Bsz, GH);
    bar_reset_kernel<<<1, 128>>>();
    sublstm_rec<<<NBLK, 256>>>(xg_p, R1, h0 + Bsz * Hd, c0 + Bsz * Hd,
                               out, hTs + Bsz * Hd, cTs + Bsz * Hd, 0);
}

// round 8
// speedup vs baseline: 1.2883x; 1.2233x over previous
#include <cuda_runtime.h>
#include <cuda_fp16.h>
#include <cstdint>
#include <cstddef>

// ---------------- problem constants ----------------
#define Hd   1024
#define Bsz  32
#define Tlen 512
#define GH   (4*Hd)
#define NBLK 128      // recurrence blocks (one per SM, single wave)
#define HPB  8        // h columns per block
#define LDP  36       // Gpart padded stride (conflict-free for our patterns)

// ---------------- device scratch (no cudaMalloc allowed) ----------------
__device__ float g_xg[(size_t)Tlen * Bsz * GH];   // 256 MB: xg for current layer
__device__ float g_a4[(size_t)Tlen * Bsz * Hd];   // 64 MB: tf32-rounded GEMM A
__device__ float g_w4[2 * (size_t)GH * Hd];       // 32 MB: tf32-rounded W0|W1
__device__ __align__(16) __half g_hx[2][Bsz * Hd]; // fp16 K-permuted h exchange (2x64KB)
__device__ unsigned g_barcnt;
__device__ volatile unsigned g_bargen;

// ---------------- small helpers ----------------
__device__ __forceinline__ uint32_t f2tf(float x) {
    uint32_t r;
    asm("cvt.rna.tf32.f32 %0, %1;" : "=r"(r) : "f"(x));
    return r;
}
__device__ __forceinline__ uint32_t pack_h2(float x, float y) {
    __half2 h = __floats2half2_rn(x, y);
    return *(uint32_t*)&h;
}
__device__ __forceinline__ float sigmoidf_(float x) {
    return 1.0f / (1.0f + __expf(-x));
}
__device__ __forceinline__ void cpasync16(float* s, const float* g) {
    uint32_t sa = (uint32_t)__cvta_generic_to_shared(s);
    asm volatile("cp.async.cg.shared.global [%0], [%1], 16;" :: "r"(sa), "l"(g));
}
__device__ __forceinline__ void cp_commit()  { asm volatile("cp.async.commit_group;"); }
__device__ __forceinline__ void cp_wait_1()  { asm volatile("cp.async.wait_group 1;"); }
__device__ __forceinline__ void cp_wait_0()  { asm volatile("cp.async.wait_group 0;"); }

__device__ __forceinline__ void mma_tf32(float* c, uint32_t a0, uint32_t a1,
                                         uint32_t a2, uint32_t a3,
                                         uint32_t b0, uint32_t b1) {
    asm volatile(
        "mma.sync.aligned.m16n8k8.row.col.f32.tf32.tf32.f32 "
        "{%0,%1,%2,%3},{%4,%5,%6,%7},{%8,%9},{%0,%1,%2,%3};"
        : "+f"(c[0]), "+f"(c[1]), "+f"(c[2]), "+f"(c[3])
        : "r"(a0), "r"(a1), "r"(a2), "r"(a3), "r"(b0), "r"(b1));
}
__device__ __forceinline__ void mma_f16(float* c, uint32_t a0, uint32_t a1,
                                        uint32_t a2, uint32_t a3,
                                        uint32_t b0, uint32_t b1) {
    asm volatile(
        "mma.sync.aligned.m16n8k16.row.col.f32.f16.f16.f32 "
        "{%0,%1,%2,%3},{%4,%5,%6,%7},{%8,%9},{%0,%1,%2,%3};"
        : "+f"(c[0]), "+f"(c[1]), "+f"(c[2]), "+f"(c[3])
        : "r"(a0), "r"(a1), "r"(a2), "r"(a3), "r"(b0), "r"(b1));
}

// grid-wide sense-reversing barrier — exact Round-3 form (passed twice).
__device__ __forceinline__ void grid_barrier() {
    __syncthreads();
    if (threadIdx.x == 0) {
        unsigned gen = g_bargen;
        __threadfence();
        if (atomicAdd(&g_barcnt, 1u) == NBLK - 1) {
            g_barcnt = 0;
            __threadfence();
            g_bargen = gen + 1;
        } else {
            while (g_bargen == gen) { }
            __threadfence();
        }
    }
    __syncthreads();
}

__global__ void bar_reset_kernel() {
    if (threadIdx.x == 0) { g_barcnt = 0; g_bargen = 0; }
}

// =====================================================================
// round-to-tf32 copy (pre-pass so GEMM needs no cvt in its hot loop)
// =====================================================================
__global__ void __launch_bounds__(256) round_tf32_kernel(
    const float* __restrict__ src, float* __restrict__ dst, int n4)
{
    int i = blockIdx.x * blockDim.x + threadIdx.x;
    int stride = gridDim.x * blockDim.x;
    for (; i < n4; i += stride) {
        float4 v = ((const float4*)src)[i];
        v.x = __uint_as_float(f2tf(v.x));
        v.y = __uint_as_float(f2tf(v.y));
        v.z = __uint_as_float(f2tf(v.z));
        v.w = __uint_as_float(f2tf(v.w));
        ((float4*)dst)[i] = v;
    }
}

// =====================================================================
// GEMM: C[M,N] = A[M,1024] @ B[N,1024]^T + bias1[N] + bias2[N]
// (Round-3 body verbatim: LDS.32 fragment loads, 64 regs, tensor ~50%.)
// =====================================================================
#define BM 128
#define BN 64
#define BK 32
#define LDT (BK + 4)

__global__ void __launch_bounds__(256) gemm_bias_tf32(
    const float* __restrict__ A, const float* __restrict__ Bw,
    const float* __restrict__ bias1, const float* __restrict__ bias2,
    float* __restrict__ C, int M, int N)
{
    extern __shared__ float sm[];
    const int K = 1024;
    float* As = sm;                 // [2][BM][LDT]
    float* Bs = sm + 2 * BM * LDT;  // [2][BN][LDT]

    const int tid  = threadIdx.x;
    const int lane = tid & 31, wid = tid >> 5;
    const int wm = wid & 3, wn = wid >> 2;       // 4 x 2 warp grid, warp tile 32x32
    const int lr = lane >> 2, lc = lane & 3;
    const int bn = blockIdx.x, bm = blockIdx.y;

    const float* Ab = A  + (size_t)bm * BM * K;
    const float* Bb = Bw + (size_t)bn * BN * K;

    float acc[2][4][4];
    #pragma unroll
    for (int i = 0; i < 2; i++)
        #pragma unroll
        for (int j = 0; j < 4; j++)
            #pragma unroll
            for (int k = 0; k < 4; k++) acc[i][j][k] = 0.f;

    auto load_tiles = [&](int st, int kb) {
        float* ad = As + st * BM * LDT;
        #pragma unroll
        for (int i = 0; i < 4; i++) {
            int s = tid + i * 256;
            int row = s >> 3, sc = s & 7;
            cpasync16(ad + row * LDT + sc * 4, Ab + (size_t)row * K + kb * BK + sc * 4);
        }
        float* bd = Bs + st * BN * LDT;
        #pragma unroll
        for (int i = 0; i < 2; i++) {
            int s = tid + i * 256;
            int row = s >> 3, sc = s & 7;
            cpasync16(bd + row * LDT + sc * 4, Bb + (size_t)row * K + kb * BK + sc * 4);
        }
    };

    load_tiles(0, 0);
    cp_commit();

    const int NKB = K / BK; // 32
    for (int kb = 0; kb < NKB; kb++) {
        if (kb + 1 < NKB) { load_tiles((kb + 1) & 1, kb + 1); cp_commit(); cp_wait_1(); }
        else              { cp_wait_0(); }
        __syncthreads();

        const float* as = As + (kb & 1) * BM * LDT + (wm * 32 + lr) * LDT + lc;
        const float* bs = Bs + (kb & 1) * BN * LDT + (wn * 32 + lr) * LDT + lc;

        #pragma unroll
        for (int kk = 0; kk < 4; kk++) {
            uint32_t a[2][4];
            #pragma unroll
            for (int mt = 0; mt < 2; mt++) {
                const float* ap = as + mt * 16 * LDT + kk * 8;
                a[mt][0] = __float_as_uint(ap[0]);
                a[mt][1] = __float_as_uint(ap[8 * LDT]);
                a[mt][2] = __float_as_uint(ap[4]);
                a[mt][3] = __float_as_uint(ap[8 * LDT + 4]);
            }
            #pragma unroll
            for (int nt = 0; nt < 4; nt++) {
                const float* bp = bs + nt * 8 * LDT + kk * 8;
                uint32_t b0 = __float_as_uint(bp[0]);
                uint32_t b1 = __float_as_uint(bp[4]);
                #pragma unroll
                for (int mt = 0; mt < 2; mt++)
                    mma_tf32(acc[mt][nt], a[mt][0], a[mt][1], a[mt][2], a[mt][3], b0, b1);
            }
        }
        __syncthreads();
    }

    #pragma unroll
    for (int mt = 0; mt < 2; mt++) {
        int m0 = bm * BM + wm * 32 + mt * 16 + lr;
        #pragma unroll
        for (int nt = 0; nt < 4; nt++) {
            int n0 = bn * BN + wn * 32 + nt * 8 + 2 * lc;
            float bv0 = bias1[n0] + bias2[n0];
            float bv1 = bias1[n0 + 1] + bias2[n0 + 1];
            float2 v0 = make_float2(acc[mt][nt][0] + bv0, acc[mt][nt][1] + bv1);
            float2 v1 = make_float2(acc[mt][nt][2] + bv0, acc[mt][nt][3] + bv1);
            *(float2*)(C + (size_t)m0 * N + n0)       = v0;
            *(float2*)(C + (size_t)(m0 + 8) * N + n0) = v1;
        }
    }
}

// =====================================================================
// Persistent subLSTM recurrence — fp16 mma (m16n8k16), f32 accumulate.
//
// fp16 round-to-nearest has the same 10-bit mantissa as tf32.rna, and
// fp16 x fp16 products are exact in the f32 accumulator, so this path
// is numerically equivalent to the verified tf32 path.
//
// h exchange buffer is fp16 with a K-permutation: within each 32-col
// chunk, storage slot 8*lc + 4*g + 2*e + d holds logical column
// 16*g + 8*e + 2*lc + d. One uint4 (8 halves) per row per chunk gives a
// lane BOTH k16-groups' A fragments with zero shuffles. R is packed to
// fp16 registers at logical k indices, so dot products are unchanged.
// =====================================================================
__global__ void __launch_bounds__(256, 1) sublstm_rec(
    const float* __restrict__ xg, const float* __restrict__ R,
    const float* __restrict__ h0, const float* __restrict__ c0,
    float* __restrict__ out, float* __restrict__ hT, float* __restrict__ cT,
    int round_output)
{
    __shared__ float Gpart[8 * 32 * LDP];   // 36,864 B

    const int tid  = threadIdx.x;
    const int lane = tid & 31;
    const int kw   = tid >> 5;              // K-split index 0..7 (128 cols each)
    const int lr   = lane >> 2, lc = lane & 3;
    const int bid  = blockIdx.x;

    // ---- R slice -> fp16 registers (once). b[f][nt] = {b0,b1}, f = k16 group ----
    uint32_t b[8][4][2];
    #pragma unroll
    for (int f = 0; f < 8; f++) {
        const int kb = kw * 128 + f * 16;
        #pragma unroll
        for (int nt = 0; nt < 4; nt++) {
            const int gr = nt * Hd + bid * HPB + lr;   // global gate row (n = lr)
            const float2 v0 = *(const float2*)(R + (size_t)gr * Hd + kb + 2 * lc);
            const float2 v1 = *(const float2*)(R + (size_t)gr * Hd + kb + 8 + 2 * lc);
            b[f][nt][0] = pack_h2(v0.x, v0.y);   // k = 2lc, 2lc+1
            b[f][nt][1] = pack_h2(v1.x, v1.y);   // k = 2lc+8, 2lc+9
        }
    }

    // ---- per-thread cell state: thread -> (batch m, local col jl) ----
    const int m  = tid >> 3;
    const int jl = tid & 7;
    const int jg = bid * HPB + jl;

    // permuted storage index for column jg (inverse of the load mapping)
    const int wv  = jg & 31, chj = jg >> 5;
    const int gj  = (wv >> 4) & 1, kkj = wv & 15;
    const int ej  = kkj >> 3, lj = (kkj & 7) >> 1, dj = kkj & 1;
    const int pj  = chj * 32 + lj * 8 + gj * 4 + ej * 2 + dj;

    float c = c0[m * Hd + jg];
    __stcg(&g_hx[0][m * Hd + pj], __float2half_rn(h0[m * Hd + jg]));

    // xg prefetch for step 0 (bh already folded into xg by the GEMM bias)
    float xv0 = __ldg(&xg[(size_t)m * GH + 0 * Hd + jg]);
    float xv1 = __ldg(&xg[(size_t)m * GH + 1 * Hd + jg]);
    float xv2 = __ldg(&xg[(size_t)m * GH + 2 * Hd + jg]);
    float xv3 = __ldg(&xg[(size_t)m * GH + 3 * Hd + jg]);

    grid_barrier();   // g_hx[0] init visible everywhere

    const int hbase = kw * 128 + lc * 8;    // half offset within a row

    for (int t = 0; t < Tlen; t++) {
        const __half* hx = g_hx[t & 1];           // read buffer
        __half* const  wh = g_hx[(t + 1) & 1];    // write buffer

        float acc[2][4][4];
        #pragma unroll
        for (int i = 0; i < 2; i++)
            #pragma unroll
            for (int j = 0; j < 4; j++)
                #pragma unroll
                for (int k = 0; k < 4; k++) acc[i][j][k] = 0.f;

        #pragma unroll
        for (int ch = 0; ch < 4; ch++) {
            // rows lr, lr+8, lr+16, lr+24 ; 8 halves each (both k16 groups)
            uint4 v[4];
            #pragma unroll
            for (int rr = 0; rr < 4; rr++)
                v[rr] = __ldcg((const uint4*)(hx + (size_t)(lr + 8 * rr) * Hd
                                                 + hbase + ch * 32));
            #pragma unroll
            for (int g = 0; g < 2; g++) {
                const int f = ch * 2 + g;
                #pragma unroll
                for (int nt = 0; nt < 4; nt++)
                    #pragma unroll
                    for (int mf = 0; mf < 2; mf++) {
                        const uint4& u0 = v[2 * mf];       // rows lr + 16mf
                        const uint4& u1 = v[2 * mf + 1];   // rows lr+8 + 16mf
                        if (g == 0)
                            mma_f16(acc[mf][nt], u0.x, u1.x, u0.y, u1.y,
                                    b[f][nt][0], b[f][nt][1]);
                        else
                            mma_f16(acc[mf][nt], u0.z, u1.z, u0.w, u1.w,
                                    b[f][nt][0], b[f][nt][1]);
                    }
            }
        }

        // ---- cross-warp K reduction via smem ----
        #pragma unroll
        for (int mf = 0; mf < 2; mf++)
            #pragma unroll
            for (int nt = 0; nt < 4; nt++)
                #pragma unroll
                for (int cc = 0; cc < 4; cc++) {
                    const int r = mf * 16 + lr + ((cc >> 1) << 3);
                    const int n = nt * 8 + 2 * lc + (cc & 1);
                    Gpart[(kw * 32 + n) * LDP + r] = acc[mf][nt][cc];
                }
        __syncthreads();

        // ---- epilogue: thread (m, jl) computes its cell ----
        float pre[4];
        #pragma unroll
        for (int g = 0; g < 4; g++) {
            const int n = g * 8 + jl;
            float s = Gpart[(0 * 32 + n) * LDP + m];
            #pragma unroll
            for (int k = 1; k < 8; k++) s += Gpart[(k * 32 + n) * LDP + m];
            pre[g] = s;
        }
        const float ig = sigmoidf_(pre[0] + xv0);
        const float og = sigmoidf_(pre[1] + xv1);
        const float zg = sigmoidf_(pre[2] + xv2);
        const float fg = sigmoidf_(pre[3] + xv3);
        c = c * fg + zg - ig;                 // subtractive cell update
        const float h = sigmoidf_(c) - og;    // subtractive output

        const __half hh = __float2half_rn(h);        // 10-bit round (== tf32.rna)
        const float  hrf = __half2float(hh);         // exactly tf32-representable

        out[(size_t)t * Bsz * Hd + m * Hd + jg] = round_output ? hrf : h;
        __stcg(&wh[m * Hd + pj], hh);
        if (t == Tlen - 1) {
            hT[m * Hd + jg] = h;
            cT[m * Hd + jg] = c;
        }

        // prefetch next step's xg while the barrier drains
        const int tn = (t + 1 < Tlen) ? t + 1 : t;
        const size_t xb = (size_t)tn * Bsz * GH + (size_t)m * GH + jg;
        xv0 = __ldg(&xg[xb + 0 * Hd]);
        xv1 = __ldg(&xg[xb + 1 * Hd]);
        xv2 = __ldg(&xg[xb + 2 * Hd]);
        xv3 = __ldg(&xg[xb + 3 * Hd]);

        grid_barrier();
    }
}

// =====================================================================
// launch
// =====================================================================
extern "C" void kernel_launch(void* const* d_in, const int* in_sizes, int n_in,
                              void* d_out, int out_size)
{
    const float* x   = (const float*)d_in[0];
    const float* h0  = (const float*)d_in[1];
    const float* c0  = (const float*)d_in[2];
    const float* W0  = (const float*)d_in[3];
    const float* R0  = (const float*)d_in[4];
    const float* bi0 = (const float*)d_in[5];
    const float* bh0 = (const float*)d_in[6];
    const float* W1  = (const float*)d_in[7];
    const float* R1  = (const float*)d_in[8];
    const float* bi1 = (const float*)d_in[9];
    const float* bh1 = (const float*)d_in[10];

    float* out = (float*)d_out;                       // [T,B,H]
    float* hTs = out + (size_t)Tlen * Bsz * Hd;       // [2,B,H]
    float* cTs = hTs + 2 * (size_t)Bsz * Hd;          // [2,B,H]

    float *xg_p, *a4_p, *w4_p;
    cudaGetSymbolAddress((void**)&xg_p, g_xg);
    cudaGetSymbolAddress((void**)&a4_p, g_a4);
    cudaGetSymbolAddress((void**)&w4_p, g_w4);

    const int SMEM_G = 2 * (BM + BN) * LDT * (int)sizeof(float);
    cudaFuncSetAttribute(gemm_bias_tf32, cudaFuncAttributeMaxDynamicSharedMemorySize, SMEM_G);

    dim3 gg(GH / BN, (Tlen * Bsz) / BM);  // (64, 128)
    const int MR = Tlen * Bsz * Hd / 4;   // float4 count for A-size arrays
    const int WR = GH * Hd / 4;           // float4 count for one W

    // pre-round weights (both layers) and layer-0 A
    round_tf32_kernel<<<512, 256>>>(W0, w4_p, WR);
    round_tf32_kernel<<<512, 256>>>(W1, w4_p + (size_t)GH * Hd, WR);
    round_tf32_kernel<<<1024, 256>>>(x, a4_p, MR);

    // layer 0: GEMM -> recurrence (hidden stream, fp16-rounded == tf32-valid,
    // lands in g_a4 which is exactly the layer-1 GEMM's A operand)
    gemm_bias_tf32<<<gg, 256, SMEM_G>>>(a4_p, w4_p, bi0, bh0, xg_p, Tlen * Bsz, GH);
    bar_reset_kernel<<<1, 32>>>();
    sublstm_rec<<<NBLK, 256>>>(xg_p, R0, h0, c0, a4_p, hTs, cTs, 1);

    // layer 1
    gemm_bias_tf32<<<gg, 256, SMEM_G>>>(a4_p, w4_p + (size_t)GH * Hd, bi1, bh1,
                                        xg_p, Tlen * Bsz, GH);
    bar_reset_kernel<<<1, 32>>>();
    sublstm_rec<<<NBLK, 256>>>(xg_p, R1, h0 + Bsz * Hd, c0 + Bsz * Hd,
                               out, hTs + Bsz * Hd, cTs + Bsz * Hd, 0);
}